// round 13
// baseline (speedup 1.0000x reference)
#include <cuda_runtime.h>
#include <cuda_bf16.h>
#include <mma.h>
#include <math.h>
#include <stdint.h>

using namespace nvcuda;

// Problem constants
#define NN 4096
#define HH 512
#define TT 12

// ---------------- scratch (device globals; no allocs allowed) ----------------
__device__ float g_h0buf[NN * HH];     // h ping
__device__ float g_h1buf[NN * HH];     // h pong
__device__ float g_gzbuf[NN * 3 * HH]; // zx @ W_ih[:, :256]^T + b_ih (time-invariant)
__device__ float g_xbuf[NN * 2];       // current action input x_t
// Split-bf16 weights, plain [w][k] row-major (w = gate*512 + j, k = 0..511)
__device__ __nv_bfloat16 g_whh_hi[3 * HH * HH];
__device__ __nv_bfloat16 g_whh_lo[3 * HH * HH];

__device__ __forceinline__ float fast_sigmoid(float v) {
    return 1.f / (1.f + __expf(-v));
}
__device__ __forceinline__ float fast_tanh(float v) {
    return 1.f - 2.f / (__expf(2.f * v) + 1.f);
}

// ---------------- merged prologue GEMM (unchanged, PASSING) ----------------
__global__ __launch_bounds__(256, 2)
void prologue_gemm(const float* __restrict__ z, const float* __restrict__ x,
                   const float* __restrict__ W_h0, const float* __restrict__ b_h0,
                   const float* __restrict__ W_ih, const float* __restrict__ b_ih,
                   float* __restrict__ h0out, float* __restrict__ gzout) {
    __shared__ float As[16][132];
    __shared__ float Bs[16][68];

    const bool is_h0 = (blockIdx.y < 8);
    const float* W   = is_h0 ? W_h0 : W_ih;
    const float* b   = is_h0 ? b_h0 : b_ih;
    float* out       = is_h0 ? h0out : gzout;
    const int ldw    = is_h0 ? 256 : 258;
    const int ncols  = is_h0 ? HH : 3 * HH;
    const int c0     = (is_h0 ? blockIdx.y : (blockIdx.y - 8)) * 64;

    const int r0 = blockIdx.x * 128;
    const int tid = threadIdx.x;
    const int ct = tid & 15;
    const int rt = tid >> 4;

    float acc[8][4];
#pragma unroll
    for (int i = 0; i < 8; i++)
#pragma unroll
        for (int j = 0; j < 4; j++) acc[i][j] = 0.f;

    for (int kb = 0; kb < 256; kb += 16) {
        const float* src = (kb < 128) ? z : x;
        const int ks = kb & 127;
#pragma unroll
        for (int t2 = 0; t2 < 2; t2++) {
            int task = tid + 256 * t2;
            int r = task >> 2;
            int k4 = (task & 3) << 2;
            float4 v = *(const float4*)&src[(size_t)(r0 + r) * 128 + ks + k4];
            As[k4 + 0][r] = v.x; As[k4 + 1][r] = v.y;
            As[k4 + 2][r] = v.z; As[k4 + 3][r] = v.w;
        }
#pragma unroll
        for (int t2 = 0; t2 < 2; t2++) {
            int e = tid + 256 * t2;
            int c = e >> 3;
            int k2 = (e & 7) << 1;
            float2 v = *(const float2*)&W[(size_t)(c0 + c) * ldw + kb + k2];
            Bs[k2 + 0][c] = v.x;
            Bs[k2 + 1][c] = v.y;
        }
        __syncthreads();
#pragma unroll
        for (int k = 0; k < 16; k++) {
            float4 a0 = *(const float4*)&As[k][rt * 8];
            float4 a1 = *(const float4*)&As[k][rt * 8 + 4];
            float a[8] = {a0.x, a0.y, a0.z, a0.w, a1.x, a1.y, a1.z, a1.w};
            float bv[4];
#pragma unroll
            for (int i = 0; i < 4; i++) bv[i] = Bs[k][ct + 16 * i];
#pragma unroll
            for (int rr = 0; rr < 8; rr++)
#pragma unroll
                for (int i = 0; i < 4; i++)
                    acc[rr][i] = fmaf(a[rr], bv[i], acc[rr][i]);
        }
        __syncthreads();
    }

#pragma unroll
    for (int i = 0; i < 4; i++) {
        int c = c0 + ct + 16 * i;
        float bb = b[c];
#pragma unroll
        for (int rr = 0; rr < 8; rr++) {
            int n = r0 + rt * 8 + rr;
            out[(size_t)n * ncols + c] = acc[rr][i] + bb;
        }
    }
}

// ---------------- W_hh -> split-bf16, plain layout (once per launch) --------
__global__ void whh_convert_kernel(const float* __restrict__ W_hh,
                                   __nv_bfloat16* __restrict__ hi,
                                   __nv_bfloat16* __restrict__ lo) {
    int idx = blockIdx.x * 256 + threadIdx.x;   // 0 .. 786431
    float v = W_hh[idx];
    __nv_bfloat16 h = __float2bfloat16(v);
    hi[idx] = h;
    lo[idx] = __float2bfloat16(v - __bfloat162float(h));
}

// ---------------- initial action ----------------
__global__ void a0_kernel(const float* __restrict__ x0,
                          const float* __restrict__ W_ia,
                          const float* __restrict__ b_ia,
                          float* __restrict__ xbuf) {
    int n = blockIdx.x * 256 + threadIdx.x;
    if (n >= NN) return;
    float4 v = *(const float4*)&x0[n * 4];
    float2 o;
    o.x = b_ia[0] + v.x * W_ia[0] + v.y * W_ia[1] + v.z * W_ia[2] + v.w * W_ia[3];
    o.y = b_ia[1] + v.x * W_ia[4] + v.y * W_ia[5] + v.z * W_ia[6] + v.w * W_ia[7];
    *(float2*)&xbuf[n * 2] = o;
}

// ---------------- wmma fused GRU step ----------------
// Block: 128 rows x 32 hidden units -> 96 gate cols. 256 threads = 8 warps.
// Warp grid 4x2: warp_m in 0..3 (32 rows), warp_n in 0..1 (48 cols).
// Split-bf16 (3 terms): gh ~= h_hi@W_hi + h_hi@W_lo + h_lo@W_hi, fp32 accum.
// A: fp32->bf16 hi/lo converted into double-buffered smem (ld=24).
// B: loaded straight from pre-converted global (col_major, ldm=512).
// C: stored to smem overlaying dead A buffers, then fused GRU gate epilogue.
__global__ __launch_bounds__(256)
void gru_step_wmma(const float* __restrict__ h_in, float* __restrict__ h_out,
                   const float* __restrict__ gz, const float* __restrict__ x_t,
                   const __nv_bfloat16* __restrict__ w_hi,
                   const __nv_bfloat16* __restrict__ w_lo,
                   const float* __restrict__ b_hh, const float* __restrict__ W_ih) {
    // 48 KB static smem: A tiles [2 buf][2 part] of 128x24 bf16 (6144 B each,
    // 24576 B total), later overlaid by C float[128][96] (49152 B).
    __shared__ __align__(16) char sm[49152];

    const int tid = threadIdx.x, wid = tid >> 5;
    const int r0 = blockIdx.x * 128, j0 = blockIdx.y * 32;
    const int warp_m = wid & 3, warp_n = wid >> 2;

    auto Atile = [&](int buf, int part) -> __nv_bfloat16* {
        return (__nv_bfloat16*)(sm + (buf * 2 + part) * 6144);
    };

    wmma::fragment<wmma::accumulator, 16, 16, 16, float> c[2][3];
#pragma unroll
    for (int mt = 0; mt < 2; mt++)
#pragma unroll
        for (int nt = 0; nt < 3; nt++)
            wmma::fill_fragment(c[mt][nt], 0.f);

    // Convert one 128x16 chunk of h into bf16 hi/lo smem tiles.
    auto convertA = [&](int buf, int kc) {
        __nv_bfloat16* hi = Atile(buf, 0);
        __nv_bfloat16* lo = Atile(buf, 1);
#pragma unroll
        for (int t2 = 0; t2 < 4; t2++) {
            int p = tid + 256 * t2;          // 0..1023 pairs
            int row = p >> 3, kp = p & 7;    // 8 pairs per row
            float2 v = *(const float2*)(h_in + (size_t)(r0 + row) * HH + kc + kp * 2);
            __nv_bfloat162 h2, l2;
            h2.x = __float2bfloat16(v.x);
            h2.y = __float2bfloat16(v.y);
            l2.x = __float2bfloat16(v.x - __bfloat162float(h2.x));
            l2.y = __float2bfloat16(v.y - __bfloat162float(h2.y));
            *(__nv_bfloat162*)(hi + row * 24 + kp * 2) = h2;
            *(__nv_bfloat162*)(lo + row * 24 + kp * 2) = l2;
        }
    };

    convertA(0, 0);
    __syncthreads();

    for (int ch = 0; ch < 32; ch++) {
        int buf = ch & 1;
        // Prefetch/convert next chunk into the other buffer (safe: the sync
        // ending the previous iteration drained all reads of that buffer).
        if (ch + 1 < 32) convertA(1 - buf, (ch + 1) * 16);

        wmma::fragment<wmma::matrix_a, 16, 16, 16, __nv_bfloat16, wmma::row_major> a_hi[2], a_lo[2];
#pragma unroll
        for (int mt = 0; mt < 2; mt++) {
            int row0 = warp_m * 32 + mt * 16;
            wmma::load_matrix_sync(a_hi[mt], Atile(buf, 0) + row0 * 24, 24);
            wmma::load_matrix_sync(a_lo[mt], Atile(buf, 1) + row0 * 24, 24);
        }
#pragma unroll
        for (int nt = 0; nt < 3; nt++) {
            int n0 = warp_n * 48 + nt * 16;          // 0..95, never straddles a gate
            int g = n0 >> 5, jj0 = n0 & 31;
            size_t wbase = (size_t)(g * HH + j0 + jj0) * HH + ch * 16;
            wmma::fragment<wmma::matrix_b, 16, 16, 16, __nv_bfloat16, wmma::col_major> b_hi, b_lo;
            wmma::load_matrix_sync(b_hi, w_hi + wbase, HH);
            wmma::load_matrix_sync(b_lo, w_lo + wbase, HH);
#pragma unroll
            for (int mt = 0; mt < 2; mt++) {
                wmma::mma_sync(c[mt][nt], a_hi[mt], b_hi, c[mt][nt]);
                wmma::mma_sync(c[mt][nt], a_hi[mt], b_lo, c[mt][nt]);
                wmma::mma_sync(c[mt][nt], a_lo[mt], b_hi, c[mt][nt]);
            }
        }
        __syncthreads();
    }

    // Store C to smem (overlaying dead A tiles; all reads drained by the
    // final loop sync).
    float* Cs = (float*)sm;
#pragma unroll
    for (int mt = 0; mt < 2; mt++)
#pragma unroll
        for (int nt = 0; nt < 3; nt++)
            wmma::store_matrix_sync(Cs + (warp_m * 32 + mt * 16) * 96 + warp_n * 48 + nt * 16,
                                    c[mt][nt], 96, wmma::mem_row_major);
    __syncthreads();

    // Fused GRU gate epilogue (math identical to the passing R8 kernel).
    const int row = tid & 127;
    const int n = r0 + row;
    const float2 xv = *(const float2*)&x_t[n * 2];
    const float* gzr = gz + (size_t)n * (3 * HH);
    const float* hir = h_in + (size_t)n * HH;
    float* hor = h_out + (size_t)n * HH;
#pragma unroll
    for (int it = 0; it < 16; it++) {
        int jj = it * 2 + (tid >> 7);   // 0..31, each thread covers 16 jj values
        int j = j0 + jj;
        float gir = __ldg(&gzr[j])
                  + xv.x * __ldg(&W_ih[(size_t)j * 258 + 256])
                  + xv.y * __ldg(&W_ih[(size_t)j * 258 + 257]);
        float giz = __ldg(&gzr[HH + j])
                  + xv.x * __ldg(&W_ih[(size_t)(HH + j) * 258 + 256])
                  + xv.y * __ldg(&W_ih[(size_t)(HH + j) * 258 + 257]);
        float gin = __ldg(&gzr[2 * HH + j])
                  + xv.x * __ldg(&W_ih[(size_t)(2 * HH + j) * 258 + 256])
                  + xv.y * __ldg(&W_ih[(size_t)(2 * HH + j) * 258 + 257]);
        float ghr = Cs[row * 96 + jj]      + __ldg(&b_hh[j]);
        float ghz = Cs[row * 96 + 32 + jj] + __ldg(&b_hh[HH + j]);
        float ghn = Cs[row * 96 + 64 + jj] + __ldg(&b_hh[2 * HH + j]);
        float rg = fast_sigmoid(gir + ghr);
        float ug = fast_sigmoid(giz + ghz);
        float ng = fast_tanh(gin + rg * ghn);
        hor[j] = ng + ug * (__ldg(&hir[j]) - ng);
    }
}

// ---------------- output projection (unchanged, PASSING) ----------------
__global__ __launch_bounds__(512)
void out_proj_kernel(const float* __restrict__ h,
                     const float* __restrict__ W_out,
                     const float* __restrict__ b_out,
                     float* __restrict__ xbuf,
                     float* __restrict__ dout, int t) {
    int tid = threadIdx.x;
    int warp = tid >> 5, lane = tid & 31;
    int n = blockIdx.x * 16 + warp;
    const float* hr = h + (size_t)n * HH;
    float s0 = 0.f, s1 = 0.f;
#pragma unroll
    for (int k = lane * 4; k < HH; k += 128) {
        float4 hv = *(const float4*)&hr[k];
        float4 w0 = *(const float4*)&W_out[k];
        float4 w1 = *(const float4*)&W_out[HH + k];
        s0 += hv.x * w0.x + hv.y * w0.y + hv.z * w0.z + hv.w * w0.w;
        s1 += hv.x * w1.x + hv.y * w1.y + hv.z * w1.z + hv.w * w1.w;
    }
#pragma unroll
    for (int off = 16; off; off >>= 1) {
        s0 += __shfl_xor_sync(0xFFFFFFFFu, s0, off);
        s1 += __shfl_xor_sync(0xFFFFFFFFu, s1, off);
    }
    if (lane == 0) {
        float2 o;
        o.x = s0 + b_out[0];
        o.y = s1 + b_out[1];
        *(float2*)&xbuf[n * 2] = o;
        *(float2*)&dout[((size_t)n * TT + t) * 2] = o;
    }
}

// ---------------- launch ----------------
extern "C" void kernel_launch(void* const* d_in, const int* in_sizes, int n_in,
                              void* d_out, int out_size) {
    const float* z     = (const float*)d_in[0];
    const float* x     = (const float*)d_in[1];
    const float* x_0   = (const float*)d_in[2];
    const float* W_ia  = (const float*)d_in[3];
    const float* b_ia  = (const float*)d_in[4];
    const float* W_h0  = (const float*)d_in[5];
    const float* b_h0  = (const float*)d_in[6];
    const float* W_ih  = (const float*)d_in[7];
    const float* b_ih  = (const float*)d_in[8];
    const float* W_hh  = (const float*)d_in[9];
    const float* b_hh  = (const float*)d_in[10];
    const float* W_out = (const float*)d_in[11];
    const float* b_out = (const float*)d_in[12];
    float* out = (float*)d_out;

    float *hA, *hB, *gzb, *xb;
    __nv_bfloat16 *whi, *wlo;
    cudaGetSymbolAddress((void**)&hA,  g_h0buf);
    cudaGetSymbolAddress((void**)&hB,  g_h1buf);
    cudaGetSymbolAddress((void**)&gzb, g_gzbuf);
    cudaGetSymbolAddress((void**)&xb,  g_xbuf);
    cudaGetSymbolAddress((void**)&whi, g_whh_hi);
    cudaGetSymbolAddress((void**)&wlo, g_whh_lo);

    // Merged prologue + weight conversion + a0
    prologue_gemm<<<dim3(NN / 128, 8 + 24), 256>>>(z, x, W_h0, b_h0, W_ih, b_ih, hA, gzb);
    whh_convert_kernel<<<(3 * HH * HH) / 256, 256>>>(W_hh, whi, wlo);
    a0_kernel<<<NN / 256, 256>>>(x_0, W_ia, b_ia, xb);

    for (int t = 0; t < TT; t++) {
        gru_step_wmma<<<dim3(NN / 128, HH / 32), 256>>>(
            hA, hB, gzb, xb, whi, wlo, b_hh, W_ih);
        out_proj_kernel<<<NN / 16, 512>>>(hB, W_out, b_out, xb, out, t);
        float* tmp = hA; hA = hB; hB = tmp;
    }
}

// round 16
// speedup vs baseline: 1.0978x; 1.0978x over previous
#include <cuda_runtime.h>
#include <cuda_bf16.h>
#include <mma.h>
#include <math.h>
#include <stdint.h>

using namespace nvcuda;

// Problem constants
#define NN 4096
#define HH 512
#define TT 12

// ---------------- scratch (device globals; no allocs allowed) ----------------
__device__ float g_h0buf[NN * HH];     // h ping
__device__ float g_h1buf[NN * HH];     // h pong
__device__ float g_gzbuf[NN * 3 * HH]; // zx @ W_ih[:, :256]^T + b_ih (time-invariant)
__device__ float g_xbuf[NN * 2];       // current action input x_t
// Split-bf16 weights, plain [w][k] row-major (w = gate*512 + j, k = 0..511)
__device__ __nv_bfloat16 g_whh_hi[3 * HH * HH];
__device__ __nv_bfloat16 g_whh_lo[3 * HH * HH];

__device__ __forceinline__ float fast_sigmoid(float v) {
    return 1.f / (1.f + __expf(-v));
}
__device__ __forceinline__ float fast_tanh(float v) {
    return 1.f - 2.f / (__expf(2.f * v) + 1.f);
}

// ---------------- merged prologue GEMM (unchanged, PASSING) ----------------
__global__ __launch_bounds__(256, 2)
void prologue_gemm(const float* __restrict__ z, const float* __restrict__ x,
                   const float* __restrict__ W_h0, const float* __restrict__ b_h0,
                   const float* __restrict__ W_ih, const float* __restrict__ b_ih,
                   float* __restrict__ h0out, float* __restrict__ gzout) {
    __shared__ float As[16][132];
    __shared__ float Bs[16][68];

    const bool is_h0 = (blockIdx.y < 8);
    const float* W   = is_h0 ? W_h0 : W_ih;
    const float* b   = is_h0 ? b_h0 : b_ih;
    float* out       = is_h0 ? h0out : gzout;
    const int ldw    = is_h0 ? 256 : 258;
    const int ncols  = is_h0 ? HH : 3 * HH;
    const int c0     = (is_h0 ? blockIdx.y : (blockIdx.y - 8)) * 64;

    const int r0 = blockIdx.x * 128;
    const int tid = threadIdx.x;
    const int ct = tid & 15;
    const int rt = tid >> 4;

    float acc[8][4];
#pragma unroll
    for (int i = 0; i < 8; i++)
#pragma unroll
        for (int j = 0; j < 4; j++) acc[i][j] = 0.f;

    for (int kb = 0; kb < 256; kb += 16) {
        const float* src = (kb < 128) ? z : x;
        const int ks = kb & 127;
#pragma unroll
        for (int t2 = 0; t2 < 2; t2++) {
            int task = tid + 256 * t2;
            int r = task >> 2;
            int k4 = (task & 3) << 2;
            float4 v = *(const float4*)&src[(size_t)(r0 + r) * 128 + ks + k4];
            As[k4 + 0][r] = v.x; As[k4 + 1][r] = v.y;
            As[k4 + 2][r] = v.z; As[k4 + 3][r] = v.w;
        }
#pragma unroll
        for (int t2 = 0; t2 < 2; t2++) {
            int e = tid + 256 * t2;
            int c = e >> 3;
            int k2 = (e & 7) << 1;
            float2 v = *(const float2*)&W[(size_t)(c0 + c) * ldw + kb + k2];
            Bs[k2 + 0][c] = v.x;
            Bs[k2 + 1][c] = v.y;
        }
        __syncthreads();
#pragma unroll
        for (int k = 0; k < 16; k++) {
            float4 a0 = *(const float4*)&As[k][rt * 8];
            float4 a1 = *(const float4*)&As[k][rt * 8 + 4];
            float a[8] = {a0.x, a0.y, a0.z, a0.w, a1.x, a1.y, a1.z, a1.w};
            float bv[4];
#pragma unroll
            for (int i = 0; i < 4; i++) bv[i] = Bs[k][ct + 16 * i];
#pragma unroll
            for (int rr = 0; rr < 8; rr++)
#pragma unroll
                for (int i = 0; i < 4; i++)
                    acc[rr][i] = fmaf(a[rr], bv[i], acc[rr][i]);
        }
        __syncthreads();
    }

#pragma unroll
    for (int i = 0; i < 4; i++) {
        int c = c0 + ct + 16 * i;
        float bb = b[c];
#pragma unroll
        for (int rr = 0; rr < 8; rr++) {
            int n = r0 + rt * 8 + rr;
            out[(size_t)n * ncols + c] = acc[rr][i] + bb;
        }
    }
}

// ---------------- W_hh -> split-bf16, plain layout (once per launch) --------
__global__ void whh_convert_kernel(const float* __restrict__ W_hh,
                                   __nv_bfloat16* __restrict__ hi,
                                   __nv_bfloat16* __restrict__ lo) {
    int idx = blockIdx.x * 256 + threadIdx.x;   // 0 .. 786431
    float v = W_hh[idx];
    __nv_bfloat16 h = __float2bfloat16(v);
    hi[idx] = h;
    lo[idx] = __float2bfloat16(v - __bfloat162float(h));
}

// ---------------- initial action ----------------
__global__ void a0_kernel(const float* __restrict__ x0,
                          const float* __restrict__ W_ia,
                          const float* __restrict__ b_ia,
                          float* __restrict__ xbuf) {
    int n = blockIdx.x * 256 + threadIdx.x;
    if (n >= NN) return;
    float4 v = *(const float4*)&x0[n * 4];
    float2 o;
    o.x = b_ia[0] + v.x * W_ia[0] + v.y * W_ia[1] + v.z * W_ia[2] + v.w * W_ia[3];
    o.y = b_ia[1] + v.x * W_ia[4] + v.y * W_ia[5] + v.z * W_ia[6] + v.w * W_ia[7];
    *(float2*)&xbuf[n * 2] = o;
}

// ---------------- wmma fused GRU step, v2: all fragments from smem ----------
// Block: 128 rows x 32 hidden units -> 96 gate cols. 256 threads = 8 warps.
// Warp grid 4x2: warp_m (32 rows), warp_n (48 cols). K-chunk = 32.
// Split-bf16 (3 terms): gh ~= h_hi@W_hi + h_hi@W_lo + h_lo@W_hi, fp32 accum.
// SMEM (dynamic 57344 B):
//   A[buf][part]: 128x32 bf16, ld=32 (8192 B each)  -> [0, 32768)
//   B[buf][part]:  96x32 bf16, ld=32 (6144 B each)  -> [32768, 57344)
//   C overlay: float[128][96] = 49152 B at base (tiles dead by then).
#define STEP_SMEM 57344
__global__ __launch_bounds__(256)
void gru_step_wmma(const float* __restrict__ h_in, float* __restrict__ h_out,
                   const float* __restrict__ gz, const float* __restrict__ x_t,
                   const __nv_bfloat16* __restrict__ w_hi,
                   const __nv_bfloat16* __restrict__ w_lo,
                   const float* __restrict__ b_hh, const float* __restrict__ W_ih) {
    extern __shared__ __align__(16) char sm[];

    const int tid = threadIdx.x, wid = tid >> 5;
    const int r0 = blockIdx.x * 128, j0 = blockIdx.y * 32;
    const int warp_m = wid & 3, warp_n = wid >> 2;

    auto Atile = [&](int buf, int part) -> __nv_bfloat16* {
        return (__nv_bfloat16*)(sm + (buf * 2 + part) * 8192);
    };
    auto Btile = [&](int buf, int part) -> __nv_bfloat16* {
        return (__nv_bfloat16*)(sm + 32768 + (buf * 2 + part) * 6144);
    };

    wmma::fragment<wmma::accumulator, 16, 16, 16, float> c[2][3];
#pragma unroll
    for (int mt = 0; mt < 2; mt++)
#pragma unroll
        for (int nt = 0; nt < 3; nt++)
            wmma::fill_fragment(c[mt][nt], 0.f);

    // Convert one 128x32 chunk of h into bf16 hi/lo smem tiles (ld=32).
    auto loadTiles = [&](int buf, int kc) {
        __nv_bfloat16* ahi = Atile(buf, 0);
        __nv_bfloat16* alo = Atile(buf, 1);
#pragma unroll
        for (int t2 = 0; t2 < 8; t2++) {
            int p = tid + 256 * t2;          // 0..2047 pairs (128 rows x 16 pairs)
            int row = p >> 4, kp = p & 15;
            float2 v = *(const float2*)(h_in + (size_t)(r0 + row) * HH + kc + kp * 2);
            __nv_bfloat162 h2, l2;
            h2.x = __float2bfloat16(v.x);
            h2.y = __float2bfloat16(v.y);
            l2.x = __float2bfloat16(v.x - __bfloat162float(h2.x));
            l2.y = __float2bfloat16(v.y - __bfloat162float(h2.y));
            *(__nv_bfloat162*)(ahi + row * 32 + kp * 2) = h2;
            *(__nv_bfloat162*)(alo + row * 32 + kp * 2) = l2;
        }
        // B: 96 w-rows x 32 k, hi+lo. Each row = 64 B = 4 int4. 384 int4/part.
        __nv_bfloat16* bhi = Btile(buf, 0);
        __nv_bfloat16* blo = Btile(buf, 1);
#pragma unroll
        for (int t2 = 0; t2 < 3; t2++) {
            int e = tid + 256 * t2;          // 0..767: part(2) x 96 rows x 4 q
            int part = e >= 384;
            int e2 = e - part * 384;
            int cc = e2 >> 2, q = e2 & 3;    // cc 0..95, q 0..3 (16B units)
            int g = cc >> 5, jj = cc & 31;
            const __nv_bfloat16* src = (part ? w_lo : w_hi)
                + (size_t)(g * HH + j0 + jj) * HH + kc + q * 8;
            __nv_bfloat16* dst = (part ? blo : bhi) + cc * 32 + q * 8;
            *(int4*)dst = *(const int4*)src;
        }
    };

    loadTiles(0, 0);
    __syncthreads();

    for (int ch = 0; ch < 16; ch++) {
        int buf = ch & 1;
        // Prefetch next chunk into the other buffer (safe: the sync ending the
        // previous iteration drained all reads of that buffer).
        if (ch + 1 < 16) loadTiles(1 - buf, (ch + 1) * 32);

#pragma unroll
        for (int ks = 0; ks < 2; ks++) {
            wmma::fragment<wmma::matrix_a, 16, 16, 16, __nv_bfloat16, wmma::row_major> a_hi[2], a_lo[2];
#pragma unroll
            for (int mt = 0; mt < 2; mt++) {
                int row0 = warp_m * 32 + mt * 16;
                wmma::load_matrix_sync(a_hi[mt], Atile(buf, 0) + row0 * 32 + ks * 16, 32);
                wmma::load_matrix_sync(a_lo[mt], Atile(buf, 1) + row0 * 32 + ks * 16, 32);
            }
#pragma unroll
            for (int nt = 0; nt < 3; nt++) {
                int cc0 = warp_n * 48 + nt * 16;   // 0..95 local gate-col
                wmma::fragment<wmma::matrix_b, 16, 16, 16, __nv_bfloat16, wmma::col_major> b_hi, b_lo;
                wmma::load_matrix_sync(b_hi, Btile(buf, 0) + cc0 * 32 + ks * 16, 32);
                wmma::load_matrix_sync(b_lo, Btile(buf, 1) + cc0 * 32 + ks * 16, 32);
#pragma unroll
                for (int mt = 0; mt < 2; mt++) {
                    wmma::mma_sync(c[mt][nt], a_hi[mt], b_hi, c[mt][nt]);
                    wmma::mma_sync(c[mt][nt], a_hi[mt], b_lo, c[mt][nt]);
                    wmma::mma_sync(c[mt][nt], a_lo[mt], b_hi, c[mt][nt]);
                }
            }
        }
        __syncthreads();
    }

    // Store C to smem (overlaying dead tiles; all reads drained by final sync).
    float* Cs = (float*)sm;
#pragma unroll
    for (int mt = 0; mt < 2; mt++)
#pragma unroll
        for (int nt = 0; nt < 3; nt++)
            wmma::store_matrix_sync(Cs + (warp_m * 32 + mt * 16) * 96 + warp_n * 48 + nt * 16,
                                    c[mt][nt], 96, wmma::mem_row_major);
    __syncthreads();

    // Fused GRU gate epilogue (math identical to the passing R8 kernel).
    const int row = tid & 127;
    const int n = r0 + row;
    const float2 xv = *(const float2*)&x_t[n * 2];
    const float* gzr = gz + (size_t)n * (3 * HH);
    const float* hir = h_in + (size_t)n * HH;
    float* hor = h_out + (size_t)n * HH;
#pragma unroll
    for (int it = 0; it < 16; it++) {
        int jj = it * 2 + (tid >> 7);   // 0..31
        int j = j0 + jj;
        float gir = __ldg(&gzr[j])
                  + xv.x * __ldg(&W_ih[(size_t)j * 258 + 256])
                  + xv.y * __ldg(&W_ih[(size_t)j * 258 + 257]);
        float giz = __ldg(&gzr[HH + j])
                  + xv.x * __ldg(&W_ih[(size_t)(HH + j) * 258 + 256])
                  + xv.y * __ldg(&W_ih[(size_t)(HH + j) * 258 + 257]);
        float gin = __ldg(&gzr[2 * HH + j])
                  + xv.x * __ldg(&W_ih[(size_t)(2 * HH + j) * 258 + 256])
                  + xv.y * __ldg(&W_ih[(size_t)(2 * HH + j) * 258 + 257]);
        float ghr = Cs[row * 96 + jj]      + __ldg(&b_hh[j]);
        float ghz = Cs[row * 96 + 32 + jj] + __ldg(&b_hh[HH + j]);
        float ghn = Cs[row * 96 + 64 + jj] + __ldg(&b_hh[2 * HH + j]);
        float rg = fast_sigmoid(gir + ghr);
        float ug = fast_sigmoid(giz + ghz);
        float ng = fast_tanh(gin + rg * ghn);
        hor[j] = ng + ug * (__ldg(&hir[j]) - ng);
    }
}

// ---------------- output projection (unchanged, PASSING) ----------------
__global__ __launch_bounds__(512)
void out_proj_kernel(const float* __restrict__ h,
                     const float* __restrict__ W_out,
                     const float* __restrict__ b_out,
                     float* __restrict__ xbuf,
                     float* __restrict__ dout, int t) {
    int tid = threadIdx.x;
    int warp = tid >> 5, lane = tid & 31;
    int n = blockIdx.x * 16 + warp;
    const float* hr = h + (size_t)n * HH;
    float s0 = 0.f, s1 = 0.f;
#pragma unroll
    for (int k = lane * 4; k < HH; k += 128) {
        float4 hv = *(const float4*)&hr[k];
        float4 w0 = *(const float4*)&W_out[k];
        float4 w1 = *(const float4*)&W_out[HH + k];
        s0 += hv.x * w0.x + hv.y * w0.y + hv.z * w0.z + hv.w * w0.w;
        s1 += hv.x * w1.x + hv.y * w1.y + hv.z * w1.z + hv.w * w1.w;
    }
#pragma unroll
    for (int off = 16; off; off >>= 1) {
        s0 += __shfl_xor_sync(0xFFFFFFFFu, s0, off);
        s1 += __shfl_xor_sync(0xFFFFFFFFu, s1, off);
    }
    if (lane == 0) {
        float2 o;
        o.x = s0 + b_out[0];
        o.y = s1 + b_out[1];
        *(float2*)&xbuf[n * 2] = o;
        *(float2*)&dout[((size_t)n * TT + t) * 2] = o;
    }
}

// ---------------- launch ----------------
extern "C" void kernel_launch(void* const* d_in, const int* in_sizes, int n_in,
                              void* d_out, int out_size) {
    const float* z     = (const float*)d_in[0];
    const float* x     = (const float*)d_in[1];
    const float* x_0   = (const float*)d_in[2];
    const float* W_ia  = (const float*)d_in[3];
    const float* b_ia  = (const float*)d_in[4];
    const float* W_h0  = (const float*)d_in[5];
    const float* b_h0  = (const float*)d_in[6];
    const float* W_ih  = (const float*)d_in[7];
    const float* b_ih  = (const float*)d_in[8];
    const float* W_hh  = (const float*)d_in[9];
    const float* b_hh  = (const float*)d_in[10];
    const float* W_out = (const float*)d_in[11];
    const float* b_out = (const float*)d_in[12];
    float* out = (float*)d_out;

    float *hA, *hB, *gzb, *xb;
    __nv_bfloat16 *whi, *wlo;
    cudaGetSymbolAddress((void**)&hA,  g_h0buf);
    cudaGetSymbolAddress((void**)&hB,  g_h1buf);
    cudaGetSymbolAddress((void**)&gzb, g_gzbuf);
    cudaGetSymbolAddress((void**)&xb,  g_xbuf);
    cudaGetSymbolAddress((void**)&whi, g_whh_hi);
    cudaGetSymbolAddress((void**)&wlo, g_whh_lo);

    cudaFuncSetAttribute(gru_step_wmma, cudaFuncAttributeMaxDynamicSharedMemorySize, STEP_SMEM);

    // Merged prologue + weight conversion + a0
    prologue_gemm<<<dim3(NN / 128, 8 + 24), 256>>>(z, x, W_h0, b_h0, W_ih, b_ih, hA, gzb);
    whh_convert_kernel<<<(3 * HH * HH) / 256, 256>>>(W_hh, whi, wlo);
    a0_kernel<<<NN / 256, 256>>>(x_0, W_ia, b_ia, xb);

    for (int t = 0; t < TT; t++) {
        gru_step_wmma<<<dim3(NN / 128, HH / 32), 256, STEP_SMEM>>>(
            hA, hB, gzb, xb, whi, wlo, b_hh, W_ih);
        out_proj_kernel<<<NN / 16, 512>>>(hB, W_out, b_out, xb, out, t);
        float* tmp = hA; hA = hB; hB = tmp;
    }
}

// round 17
// speedup vs baseline: 1.5746x; 1.4343x over previous
#include <cuda_runtime.h>
#include <cuda_bf16.h>
#include <mma.h>
#include <math.h>
#include <stdint.h>

using namespace nvcuda;

// Problem constants
#define NN 4096
#define HH 512
#define TT 12

// ---------------- scratch (device globals; no allocs allowed) ----------------
__device__ float g_h0buf[NN * HH];     // h ping
__device__ float g_h1buf[NN * HH];     // h pong
__device__ float g_gzbuf[NN * 3 * HH]; // zx @ W_ih[:, :256]^T + b_ih (time-invariant)
__device__ float g_xbuf[NN * 2];       // current action input x_t
// Split-bf16 weights, plain [w][k] row-major (w = gate*512 + j, k = 0..511)
__device__ __nv_bfloat16 g_whh_hi[3 * HH * HH];
__device__ __nv_bfloat16 g_whh_lo[3 * HH * HH];

__device__ __forceinline__ float fast_sigmoid(float v) {
    return 1.f / (1.f + __expf(-v));
}
__device__ __forceinline__ float fast_tanh(float v) {
    return 1.f - 2.f / (__expf(2.f * v) + 1.f);
}

// ---------------- merged prologue GEMM (unchanged, PASSING) ----------------
__global__ __launch_bounds__(256, 2)
void prologue_gemm(const float* __restrict__ z, const float* __restrict__ x,
                   const float* __restrict__ W_h0, const float* __restrict__ b_h0,
                   const float* __restrict__ W_ih, const float* __restrict__ b_ih,
                   float* __restrict__ h0out, float* __restrict__ gzout) {
    __shared__ float As[16][132];
    __shared__ float Bs[16][68];

    const bool is_h0 = (blockIdx.y < 8);
    const float* W   = is_h0 ? W_h0 : W_ih;
    const float* b   = is_h0 ? b_h0 : b_ih;
    float* out       = is_h0 ? h0out : gzout;
    const int ldw    = is_h0 ? 256 : 258;
    const int ncols  = is_h0 ? HH : 3 * HH;
    const int c0     = (is_h0 ? blockIdx.y : (blockIdx.y - 8)) * 64;

    const int r0 = blockIdx.x * 128;
    const int tid = threadIdx.x;
    const int ct = tid & 15;
    const int rt = tid >> 4;

    float acc[8][4];
#pragma unroll
    for (int i = 0; i < 8; i++)
#pragma unroll
        for (int j = 0; j < 4; j++) acc[i][j] = 0.f;

    for (int kb = 0; kb < 256; kb += 16) {
        const float* src = (kb < 128) ? z : x;
        const int ks = kb & 127;
#pragma unroll
        for (int t2 = 0; t2 < 2; t2++) {
            int task = tid + 256 * t2;
            int r = task >> 2;
            int k4 = (task & 3) << 2;
            float4 v = *(const float4*)&src[(size_t)(r0 + r) * 128 + ks + k4];
            As[k4 + 0][r] = v.x; As[k4 + 1][r] = v.y;
            As[k4 + 2][r] = v.z; As[k4 + 3][r] = v.w;
        }
#pragma unroll
        for (int t2 = 0; t2 < 2; t2++) {
            int e = tid + 256 * t2;
            int c = e >> 3;
            int k2 = (e & 7) << 1;
            float2 v = *(const float2*)&W[(size_t)(c0 + c) * ldw + kb + k2];
            Bs[k2 + 0][c] = v.x;
            Bs[k2 + 1][c] = v.y;
        }
        __syncthreads();
#pragma unroll
        for (int k = 0; k < 16; k++) {
            float4 a0 = *(const float4*)&As[k][rt * 8];
            float4 a1 = *(const float4*)&As[k][rt * 8 + 4];
            float a[8] = {a0.x, a0.y, a0.z, a0.w, a1.x, a1.y, a1.z, a1.w};
            float bv[4];
#pragma unroll
            for (int i = 0; i < 4; i++) bv[i] = Bs[k][ct + 16 * i];
#pragma unroll
            for (int rr = 0; rr < 8; rr++)
#pragma unroll
                for (int i = 0; i < 4; i++)
                    acc[rr][i] = fmaf(a[rr], bv[i], acc[rr][i]);
        }
        __syncthreads();
    }

#pragma unroll
    for (int i = 0; i < 4; i++) {
        int c = c0 + ct + 16 * i;
        float bb = b[c];
#pragma unroll
        for (int rr = 0; rr < 8; rr++) {
            int n = r0 + rt * 8 + rr;
            out[(size_t)n * ncols + c] = acc[rr][i] + bb;
        }
    }
}

// ---------------- W_hh -> split-bf16, plain layout (once per launch) --------
__global__ void whh_convert_kernel(const float* __restrict__ W_hh,
                                   __nv_bfloat16* __restrict__ hi,
                                   __nv_bfloat16* __restrict__ lo) {
    int idx = blockIdx.x * 256 + threadIdx.x;   // 0 .. 786431
    float v = W_hh[idx];
    __nv_bfloat16 h = __float2bfloat16(v);
    hi[idx] = h;
    lo[idx] = __float2bfloat16(v - __bfloat162float(h));
}

// ---------------- initial action ----------------
__global__ void a0_kernel(const float* __restrict__ x0,
                          const float* __restrict__ W_ia,
                          const float* __restrict__ b_ia,
                          float* __restrict__ xbuf) {
    int n = blockIdx.x * 256 + threadIdx.x;
    if (n >= NN) return;
    float4 v = *(const float4*)&x0[n * 4];
    float2 o;
    o.x = b_ia[0] + v.x * W_ia[0] + v.y * W_ia[1] + v.z * W_ia[2] + v.w * W_ia[3];
    o.y = b_ia[1] + v.x * W_ia[4] + v.y * W_ia[5] + v.z * W_ia[6] + v.w * W_ia[7];
    *(float2*)&xbuf[n * 2] = o;
}

// ---------------- wmma fused GRU step, v3: conflict-free padded tiles -------
// Block: 128 rows x 32 hidden units -> 96 gate cols. 256 threads = 8 warps.
// Warp grid 4x2: warp_m (32 rows), warp_n (48 cols). K-chunk = 32.
// Split-bf16 (3 terms): gh ~= h_hi@W_hi + h_hi@W_lo + h_lo@W_hi, fp32 accum.
// PADDING: tile ld = 40 elements (80 B rows). 80*r mod 128 cycles through all
// eight 16B bank slots -> LDSM conflict-free (ld=32 had 4-way conflicts).
// C overlay ld = 100 floats (400 B rows, 400 mod 128 = 16 -> conflict-free).
// SMEM (dynamic 71680 B):
//   A[buf][part]: 128x40 bf16 (10240 B each) -> [0, 40960)
//   B[buf][part]:  96x40 bf16 ( 7680 B each) -> [40960, 71680)
//   C overlay: float[128][100] = 51200 B at base (tiles dead by then).
#define LDA 40
#define LDC 100
#define STEP_SMEM 71680
__global__ __launch_bounds__(256)
void gru_step_wmma(const float* __restrict__ h_in, float* __restrict__ h_out,
                   const float* __restrict__ gz, const float* __restrict__ x_t,
                   const __nv_bfloat16* __restrict__ w_hi,
                   const __nv_bfloat16* __restrict__ w_lo,
                   const float* __restrict__ b_hh, const float* __restrict__ W_ih) {
    extern __shared__ __align__(16) char sm[];

    const int tid = threadIdx.x, wid = tid >> 5;
    const int r0 = blockIdx.x * 128, j0 = blockIdx.y * 32;
    const int warp_m = wid & 3, warp_n = wid >> 2;

    auto Atile = [&](int buf, int part) -> __nv_bfloat16* {
        return (__nv_bfloat16*)(sm + (buf * 2 + part) * 10240);
    };
    auto Btile = [&](int buf, int part) -> __nv_bfloat16* {
        return (__nv_bfloat16*)(sm + 40960 + (buf * 2 + part) * 7680);
    };

    wmma::fragment<wmma::accumulator, 16, 16, 16, float> c[2][3];
#pragma unroll
    for (int mt = 0; mt < 2; mt++)
#pragma unroll
        for (int nt = 0; nt < 3; nt++)
            wmma::fill_fragment(c[mt][nt], 0.f);

    // Convert one 128x32 chunk of h into bf16 hi/lo smem tiles (ld=40).
    auto loadTiles = [&](int buf, int kc) {
        __nv_bfloat16* ahi = Atile(buf, 0);
        __nv_bfloat16* alo = Atile(buf, 1);
#pragma unroll
        for (int t2 = 0; t2 < 8; t2++) {
            int p = tid + 256 * t2;          // 0..2047 pairs (128 rows x 16 pairs)
            int row = p >> 4, kp = p & 15;
            float2 v = *(const float2*)(h_in + (size_t)(r0 + row) * HH + kc + kp * 2);
            __nv_bfloat162 h2, l2;
            h2.x = __float2bfloat16(v.x);
            h2.y = __float2bfloat16(v.y);
            l2.x = __float2bfloat16(v.x - __bfloat162float(h2.x));
            l2.y = __float2bfloat16(v.y - __bfloat162float(h2.y));
            *(__nv_bfloat162*)(ahi + row * LDA + kp * 2) = h2;
            *(__nv_bfloat162*)(alo + row * LDA + kp * 2) = l2;
        }
        // B: 96 w-rows x 32 k, hi+lo. Each row = 4 int4 of data (ld padded to 40).
        __nv_bfloat16* bhi = Btile(buf, 0);
        __nv_bfloat16* blo = Btile(buf, 1);
#pragma unroll
        for (int t2 = 0; t2 < 3; t2++) {
            int e = tid + 256 * t2;          // 0..767: part(2) x 96 rows x 4 q
            int part = e >= 384;
            int e2 = e - part * 384;
            int cc = e2 >> 2, q = e2 & 3;    // cc 0..95, q 0..3 (16B units)
            int g = cc >> 5, jj = cc & 31;
            const __nv_bfloat16* src = (part ? w_lo : w_hi)
                + (size_t)(g * HH + j0 + jj) * HH + kc + q * 8;
            __nv_bfloat16* dst = (part ? blo : bhi) + cc * LDA + q * 8;
            *(int4*)dst = *(const int4*)src;   // cc*80 bytes: 16B-aligned
        }
    };

    loadTiles(0, 0);
    __syncthreads();

    for (int ch = 0; ch < 16; ch++) {
        int buf = ch & 1;
        // Prefetch next chunk into the other buffer (safe: the sync ending the
        // previous iteration drained all reads of that buffer).
        if (ch + 1 < 16) loadTiles(1 - buf, (ch + 1) * 32);

#pragma unroll
        for (int ks = 0; ks < 2; ks++) {
            wmma::fragment<wmma::matrix_a, 16, 16, 16, __nv_bfloat16, wmma::row_major> a_hi[2], a_lo[2];
#pragma unroll
            for (int mt = 0; mt < 2; mt++) {
                int row0 = warp_m * 32 + mt * 16;
                wmma::load_matrix_sync(a_hi[mt], Atile(buf, 0) + row0 * LDA + ks * 16, LDA);
                wmma::load_matrix_sync(a_lo[mt], Atile(buf, 1) + row0 * LDA + ks * 16, LDA);
            }
#pragma unroll
            for (int nt = 0; nt < 3; nt++) {
                int cc0 = warp_n * 48 + nt * 16;   // 0..95 local gate-col
                wmma::fragment<wmma::matrix_b, 16, 16, 16, __nv_bfloat16, wmma::col_major> b_hi, b_lo;
                wmma::load_matrix_sync(b_hi, Btile(buf, 0) + cc0 * LDA + ks * 16, LDA);
                wmma::load_matrix_sync(b_lo, Btile(buf, 1) + cc0 * LDA + ks * 16, LDA);
#pragma unroll
                for (int mt = 0; mt < 2; mt++) {
                    wmma::mma_sync(c[mt][nt], a_hi[mt], b_hi, c[mt][nt]);
                    wmma::mma_sync(c[mt][nt], a_hi[mt], b_lo, c[mt][nt]);
                    wmma::mma_sync(c[mt][nt], a_lo[mt], b_hi, c[mt][nt]);
                }
            }
        }
        __syncthreads();
    }

    // Store C to smem (overlaying dead tiles; all reads drained by final sync).
    float* Cs = (float*)sm;
#pragma unroll
    for (int mt = 0; mt < 2; mt++)
#pragma unroll
        for (int nt = 0; nt < 3; nt++)
            wmma::store_matrix_sync(Cs + (warp_m * 32 + mt * 16) * LDC + warp_n * 48 + nt * 16,
                                    c[mt][nt], LDC, wmma::mem_row_major);
    __syncthreads();

    // Fused GRU gate epilogue (math identical to the passing R8 kernel).
    const int row = tid & 127;
    const int n = r0 + row;
    const float2 xv = *(const float2*)&x_t[n * 2];
    const float* gzr = gz + (size_t)n * (3 * HH);
    const float* hir = h_in + (size_t)n * HH;
    float* hor = h_out + (size_t)n * HH;
#pragma unroll
    for (int it = 0; it < 16; it++) {
        int jj = it * 2 + (tid >> 7);   // 0..31
        int j = j0 + jj;
        float gir = __ldg(&gzr[j])
                  + xv.x * __ldg(&W_ih[(size_t)j * 258 + 256])
                  + xv.y * __ldg(&W_ih[(size_t)j * 258 + 257]);
        float giz = __ldg(&gzr[HH + j])
                  + xv.x * __ldg(&W_ih[(size_t)(HH + j) * 258 + 256])
                  + xv.y * __ldg(&W_ih[(size_t)(HH + j) * 258 + 257]);
        float gin = __ldg(&gzr[2 * HH + j])
                  + xv.x * __ldg(&W_ih[(size_t)(2 * HH + j) * 258 + 256])
                  + xv.y * __ldg(&W_ih[(size_t)(2 * HH + j) * 258 + 257]);
        float ghr = Cs[row * LDC + jj]      + __ldg(&b_hh[j]);
        float ghz = Cs[row * LDC + 32 + jj] + __ldg(&b_hh[HH + j]);
        float ghn = Cs[row * LDC + 64 + jj] + __ldg(&b_hh[2 * HH + j]);
        float rg = fast_sigmoid(gir + ghr);
        float ug = fast_sigmoid(giz + ghz);
        float ng = fast_tanh(gin + rg * ghn);
        hor[j] = ng + ug * (__ldg(&hir[j]) - ng);
    }
}

// ---------------- output projection (unchanged, PASSING) ----------------
__global__ __launch_bounds__(512)
void out_proj_kernel(const float* __restrict__ h,
                     const float* __restrict__ W_out,
                     const float* __restrict__ b_out,
                     float* __restrict__ xbuf,
                     float* __restrict__ dout, int t) {
    int tid = threadIdx.x;
    int warp = tid >> 5, lane = tid & 31;
    int n = blockIdx.x * 16 + warp;
    const float* hr = h + (size_t)n * HH;
    float s0 = 0.f, s1 = 0.f;
#pragma unroll
    for (int k = lane * 4; k < HH; k += 128) {
        float4 hv = *(const float4*)&hr[k];
        float4 w0 = *(const float4*)&W_out[k];
        float4 w1 = *(const float4*)&W_out[HH + k];
        s0 += hv.x * w0.x + hv.y * w0.y + hv.z * w0.z + hv.w * w0.w;
        s1 += hv.x * w1.x + hv.y * w1.y + hv.z * w1.z + hv.w * w1.w;
    }
#pragma unroll
    for (int off = 16; off; off >>= 1) {
        s0 += __shfl_xor_sync(0xFFFFFFFFu, s0, off);
        s1 += __shfl_xor_sync(0xFFFFFFFFu, s1, off);
    }
    if (lane == 0) {
        float2 o;
        o.x = s0 + b_out[0];
        o.y = s1 + b_out[1];
        *(float2*)&xbuf[n * 2] = o;
        *(float2*)&dout[((size_t)n * TT + t) * 2] = o;
    }
}

// ---------------- launch ----------------
extern "C" void kernel_launch(void* const* d_in, const int* in_sizes, int n_in,
                              void* d_out, int out_size) {
    const float* z     = (const float*)d_in[0];
    const float* x     = (const float*)d_in[1];
    const float* x_0   = (const float*)d_in[2];
    const float* W_ia  = (const float*)d_in[3];
    const float* b_ia  = (const float*)d_in[4];
    const float* W_h0  = (const float*)d_in[5];
    const float* b_h0  = (const float*)d_in[6];
    const float* W_ih  = (const float*)d_in[7];
    const float* b_ih  = (const float*)d_in[8];
    const float* W_hh  = (const float*)d_in[9];
    const float* b_hh  = (const float*)d_in[10];
    const float* W_out = (const float*)d_in[11];
    const float* b_out = (const float*)d_in[12];
    float* out = (float*)d_out;

    float *hA, *hB, *gzb, *xb;
    __nv_bfloat16 *whi, *wlo;
    cudaGetSymbolAddress((void**)&hA,  g_h0buf);
    cudaGetSymbolAddress((void**)&hB,  g_h1buf);
    cudaGetSymbolAddress((void**)&gzb, g_gzbuf);
    cudaGetSymbolAddress((void**)&xb,  g_xbuf);
    cudaGetSymbolAddress((void**)&whi, g_whh_hi);
    cudaGetSymbolAddress((void**)&wlo, g_whh_lo);

    cudaFuncSetAttribute(gru_step_wmma, cudaFuncAttributeMaxDynamicSharedMemorySize, STEP_SMEM);

    // Merged prologue + weight conversion + a0
    prologue_gemm<<<dim3(NN / 128, 8 + 24), 256>>>(z, x, W_h0, b_h0, W_ih, b_ih, hA, gzb);
    whh_convert_kernel<<<(3 * HH * HH) / 256, 256>>>(W_hh, whi, wlo);
    a0_kernel<<<NN / 256, 256>>>(x_0, W_ia, b_ia, xb);

    for (int t = 0; t < TT; t++) {
        gru_step_wmma<<<dim3(NN / 128, HH / 32), 256, STEP_SMEM>>>(
            hA, hB, gzb, xb, whi, wlo, b_hh, W_ih);
        out_proj_kernel<<<NN / 16, 512>>>(hB, W_out, b_out, xb, out, t);
        float* tmp = hA; hA = hB; hB = tmp;
    }
}